// round 2
// baseline (speedup 1.0000x reference)
#include <cuda_runtime.h>
#include <cstdint>

// LSTM_86440511800183: T=8192 sequential LSTM, H=40, input=1, output=1, batch=1.
// Pure latency problem: single persistent CTA, 160 threads (one per gate row),
// W_hh rows in registers as packed f32x2 pairs, h double-buffered in shared,
// c in registers, one __syncthreads per timestep, intra-warp gate exchange via
// shfl, dot product via Blackwell packed fma.rn.f32x2 (SASS FFMA2, PTX-only).

#define T_MAX 8192
#define HID   40
#define NROW  160   // 4*HID

__device__ __forceinline__ float sig_f(float x) {
    // 1/(1+e^{-x}); __expf ~2ulp, __fdividef fine (denominator in [1, inf))
    return __fdividef(1.0f, 1.0f + __expf(-x));
}
__device__ __forceinline__ float tanh_f(float x) {
    // 1 - 2/(e^{2x}+1): saturates correctly at +/-1 for large |x| (expf -> inf/0)
    return 1.0f - __fdividef(2.0f, __expf(2.0f * x) + 1.0f);
}

// d += a * b, packed 2xf32 (SASS FFMA2; halves dot-product issue count)
__device__ __forceinline__ void ffma2(uint64_t& d, uint64_t a, uint64_t b) {
    asm("fma.rn.f32x2 %0, %1, %2, %0;" : "+l"(d) : "l"(a), "l"(b));
}
__device__ __forceinline__ uint64_t fadd2(uint64_t a, uint64_t b) {
    uint64_t r;
    asm("add.rn.f32x2 %0, %1, %2;" : "=l"(r) : "l"(a), "l"(b));
    return r;
}
__device__ __forceinline__ void unpack2(float& lo, float& hi, uint64_t v) {
    asm("mov.b64 {%0, %1}, %2;" : "=f"(lo), "=f"(hi) : "l"(v));
}

__global__ __launch_bounds__(NROW, 1)
void lstm_seq_kernel(const float* __restrict__ x,
                     const float* __restrict__ W_ih,
                     const float* __restrict__ W_hh,
                     const float* __restrict__ b_ih,
                     const float* __restrict__ b_hh,
                     const float* __restrict__ W_lin,
                     const float* __restrict__ b_lin,
                     float* __restrict__ out,
                     int T)
{
    __shared__ float      xs[T_MAX];
    __shared__ ulonglong2 hbuf[2][HID / 4];   // double-buffered hidden state (40 f32 = 10x16B)

    const int tid  = threadIdx.x;
    const int w    = tid >> 5;
    const int lane = tid & 31;
    const int gate = lane >> 3;         // 0:i 1:f 2:g 3:o
    const int uu   = lane & 7;
    const int unit = w * 8 + uu;        // 0..39
    const int row  = gate * HID + unit; // 0..159 row of W_hh / W_ih / biases

    // Stage the whole input sequence into shared memory once.
    for (int i = tid; i < T && i < T_MAX; i += NROW) xs[i] = x[i];

    // Per-thread recurrent weight row in registers as 20 packed f32x2 pairs
    // (row*160B is 16B-aligned, so ulonglong2 loads are legal).
    uint64_t wp[HID / 2];
    {
        const ulonglong2* wrow = reinterpret_cast<const ulonglong2*>(W_hh + row * HID);
        #pragma unroll
        for (int k = 0; k < HID / 4; k++) {
            ulonglong2 v = wrow[k];
            wp[2 * k]     = v.x;
            wp[2 * k + 1] = v.y;
        }
    }

    const float wih  = W_ih[row];               // input_size == 1
    const float bias = b_ih[row] + b_hh[row];   // fold both biases

    // Zero initial hidden state buffer 0.
    if (tid < HID / 4) hbuf[0][tid] = make_ulonglong2(0ull, 0ull);
    float c = 0.0f;   // cell state, owned by gate==0 lanes (one per unit)
    __syncthreads();

    int p = 0;
    for (int t = 0; t < T; t++) {
        // ---- gate pre-activation: W_hh[row] . h  (+ x[t]*W_ih[row] + bias) ----
        // One LDS.128 yields two pre-packed f32x2 operands; two independent
        // FFMA2 accumulator chains (10 deep each, lat 4 -> ~40cy chain).
        const ulonglong2* h2 = hbuf[p];
        uint64_t acc0 = 0ull, acc1 = 0ull;   // f32x2 {0,0}
        #pragma unroll
        for (int k = 0; k < HID / 4; k++) {
            ulonglong2 hv = h2[k];
            ffma2(acc0, wp[2 * k],     hv.x);
            ffma2(acc1, wp[2 * k + 1], hv.y);
        }
        float s0, s1;
        unpack2(s0, s1, fadd2(acc0, acc1));
        float acc = (s0 + s1) + fmaf(xs[t], wih, bias);

        // ---- intra-warp gate exchange: 4 gate rows of this unit live in this warp ----
        const unsigned FULL = 0xffffffffu;
        float gi = __shfl_sync(FULL, acc, uu);
        float gf = __shfl_sync(FULL, acc, uu + 8);
        float gc = __shfl_sync(FULL, acc, uu + 16);
        float go = __shfl_sync(FULL, acc, uu + 24);

        // ---- state update on the owning lane; write h to the OTHER buffer ----
        float* hn = reinterpret_cast<float*>(hbuf[p ^ 1]);
        if (gate == 0) {
            float i_ = sig_f(gi);
            float f_ = sig_f(gf);
            float g_ = tanh_f(gc);
            float o_ = sig_f(go);
            c = fmaf(f_, c, i_ * g_);
            hn[unit] = o_ * tanh_f(c);
        }
        p ^= 1;
        __syncthreads();   // h_new visible to all warps; old buffer now writable
    }

    // ---- final linear: out = h_T . W_lin + b_lin  (OUT == 1, one-time cost) ----
    if (tid == 0) {
        const float* hf = reinterpret_cast<const float*>(hbuf[p]);
        float s = b_lin[0];
        #pragma unroll
        for (int k = 0; k < HID; k++) s = fmaf(hf[k], W_lin[k], s);
        out[0] = s;
    }
}

extern "C" void kernel_launch(void* const* d_in, const int* in_sizes, int n_in,
                              void* d_out, int out_size)
{
    const float* x     = (const float*)d_in[0]; // input_seq [T,1]
    const float* W_ih  = (const float*)d_in[1]; // [160,1]
    const float* W_hh  = (const float*)d_in[2]; // [160,40]
    const float* b_ih  = (const float*)d_in[3]; // [160]
    const float* b_hh  = (const float*)d_in[4]; // [160]
    const float* W_lin = (const float*)d_in[5]; // [1,40]
    const float* b_lin = (const float*)d_in[6]; // [1]
    float* out = (float*)d_out;

    int T = in_sizes[0];  // T*INPUT = 8192
    lstm_seq_kernel<<<1, NROW>>>(x, W_ih, W_hh, b_ih, b_hh, W_lin, b_lin, out, T);
}

// round 3
// speedup vs baseline: 1.0353x; 1.0353x over previous
#include <cuda_runtime.h>
#include <cstdint>

// LSTM_86440511800183: T=8192 sequential LSTM, H=40, input=1, output=1, batch=1.
// Single persistent CTA, 160 threads (one per gate row), W_hh rows in registers
// as packed f32x2, h double-buffered in shared, c in registers, one
// __syncthreads per step.
// R3 change: unified per-lane activation BEFORE the gate shfl (one warp-wide
// EX2 + RCP covers all 4 gates) -> MUFU warp-instrs per step 10 -> 4, and the
// serial activation chain halves. Dot product split into 4 FFMA2 chains of 5.

#define T_MAX 8192
#define HID   40
#define NROW  160   // 4*HID

#define LOG2E 1.4426950408889634f

// d += a * b, packed 2xf32 (SASS FFMA2; halves dot-product issue count)
__device__ __forceinline__ void ffma2(uint64_t& d, uint64_t a, uint64_t b) {
    asm("fma.rn.f32x2 %0, %1, %2, %0;" : "+l"(d) : "l"(a), "l"(b));
}
__device__ __forceinline__ uint64_t fadd2(uint64_t a, uint64_t b) {
    uint64_t r;
    asm("add.rn.f32x2 %0, %1, %2;" : "=l"(r) : "l"(a), "l"(b));
    return r;
}
__device__ __forceinline__ void unpack2(float& lo, float& hi, uint64_t v) {
    asm("mov.b64 {%0, %1}, %2;" : "=f"(lo), "=f"(hi) : "l"(v));
}
__device__ __forceinline__ float ex2_f(float x) {
    float r; asm("ex2.approx.f32 %0, %1;" : "=f"(r) : "f"(x)); return r;
}
__device__ __forceinline__ float rcp_f(float x) {
    float r; asm("rcp.approx.f32 %0, %1;" : "=f"(r) : "f"(x)); return r;
}

__global__ __launch_bounds__(NROW, 1)
void lstm_seq_kernel(const float* __restrict__ x,
                     const float* __restrict__ W_ih,
                     const float* __restrict__ W_hh,
                     const float* __restrict__ b_ih,
                     const float* __restrict__ b_hh,
                     const float* __restrict__ W_lin,
                     const float* __restrict__ b_lin,
                     float* __restrict__ out,
                     int T)
{
    __shared__ float      xs[T_MAX];
    __shared__ ulonglong2 hbuf[2][HID / 4];   // double-buffered hidden state

    const int tid  = threadIdx.x;
    const int w    = tid >> 5;
    const int lane = tid & 31;
    const int gate = lane >> 3;         // 0:i 1:f 2:g 3:o
    const int uu   = lane & 7;
    const int unit = w * 8 + uu;        // 0..39
    const int row  = gate * HID + unit; // 0..159

    // Stage the whole input sequence into shared once.
    for (int i = tid; i < T && i < T_MAX; i += NROW) xs[i] = x[i];

    // Per-thread recurrent weight row as 20 packed f32x2 pairs.
    uint64_t wp[HID / 2];
    {
        const ulonglong2* wrow = reinterpret_cast<const ulonglong2*>(W_hh + row * HID);
        #pragma unroll
        for (int k = 0; k < HID / 4; k++) {
            ulonglong2 v = wrow[k];
            wp[2 * k]     = v.x;
            wp[2 * k + 1] = v.y;
        }
    }

    const float wih  = W_ih[row];
    const float bias = b_ih[row] + b_hh[row];

    // Unified activation constants: act = fma(A, rcp(1 + ex2(M*x)), B)
    //  sigmoid (gates i,f,o): u = 1/(1+e^-x)   -> M=-log2e,  A=1, B=0
    //  tanh    (gate g):      2/(1+e^-2x) - 1  -> M=-2log2e, A=2, B=-1
    const float M = (gate == 2) ? (-2.0f * LOG2E) : (-LOG2E);
    const float A = (gate == 2) ? 2.0f : 1.0f;
    const float B = (gate == 2) ? -1.0f : 0.0f;

    if (tid < HID / 4) hbuf[0][tid] = make_ulonglong2(0ull, 0ull);
    float c = 0.0f;   // cell state, owned by gate==0 lanes
    __syncthreads();

    const unsigned FULL = 0xffffffffu;
    int p = 0;
    for (int t = 0; t < T; t++) {
        // ---- gate pre-activation: W_hh[row].h + x[t]*W_ih[row] + bias ----
        // 4 independent FFMA2 chains of depth 5 (chain ~20cy).
        const ulonglong2* h2 = hbuf[p];
        uint64_t a0 = 0ull, a1 = 0ull, a2 = 0ull, a3 = 0ull;
        #pragma unroll
        for (int k = 0; k < HID / 4; k += 2) {
            ulonglong2 hv0 = h2[k];
            ulonglong2 hv1 = h2[k + 1];
            ffma2(a0, wp[2 * k],     hv0.x);
            ffma2(a1, wp[2 * k + 1], hv0.y);
            ffma2(a2, wp[2 * k + 2], hv1.x);
            ffma2(a3, wp[2 * k + 3], hv1.y);
        }
        uint64_t s = fadd2(fadd2(a0, a2), fadd2(a1, a3));
        float s0, s1;
        unpack2(s0, s1, s);
        float acc = (s0 + s1) + fmaf(xs[t], wih, bias);

        // ---- per-lane unified activation (one warp-wide EX2 + RCP) ----
        float u   = rcp_f(1.0f + ex2_f(acc * M));
        float act = fmaf(A, u, B);   // i/f/o: sigmoid(acc); g: tanh(acc)

        // ---- exchange ACTIVATED gate values within the warp ----
        float f_ = __shfl_sync(FULL, act, uu + 8);
        float g_ = __shfl_sync(FULL, act, uu + 16);
        float o_ = __shfl_sync(FULL, act, uu + 24);
        // owner lane's own act is i_

        // ---- state update on owner lane; write h to other buffer ----
        float* hn = reinterpret_cast<float*>(hbuf[p ^ 1]);
        if (gate == 0) {
            float ig = act * g_;
            c = fmaf(f_, c, ig);
            float u2 = rcp_f(1.0f + ex2_f(c * (-2.0f * LOG2E)));
            float tc = fmaf(2.0f, u2, -1.0f);   // tanh(c)
            hn[unit] = o_ * tc;
        }
        p ^= 1;
        __syncthreads();
    }

    // ---- final linear: out = h_T . W_lin + b_lin ----
    if (tid == 0) {
        const float* hf = reinterpret_cast<const float*>(hbuf[p]);
        float sum = b_lin[0];
        #pragma unroll
        for (int k = 0; k < HID; k++) sum = fmaf(hf[k], W_lin[k], sum);
        out[0] = sum;
    }
}

extern "C" void kernel_launch(void* const* d_in, const int* in_sizes, int n_in,
                              void* d_out, int out_size)
{
    const float* x     = (const float*)d_in[0]; // input_seq [T,1]
    const float* W_ih  = (const float*)d_in[1]; // [160,1]
    const float* W_hh  = (const float*)d_in[2]; // [160,40]
    const float* b_ih  = (const float*)d_in[3]; // [160]
    const float* b_hh  = (const float*)d_in[4]; // [160]
    const float* W_lin = (const float*)d_in[5]; // [1,40]
    const float* b_lin = (const float*)d_in[6]; // [1]
    float* out = (float*)d_out;

    int T = in_sizes[0];
    lstm_seq_kernel<<<1, NROW>>>(x, W_ih, W_hh, b_ih, b_hh, W_lin, b_lin, out, T);
}

// round 4
// speedup vs baseline: 1.5558x; 1.5027x over previous
#include <cuda_runtime.h>
#include <cstdint>

// LSTM_86440511800183: T=8192 sequential LSTM, H=40, input=1, output=1, batch=1.
// Single persistent CTA, 160 threads (one per gate row). Latency-chain-bound
// (~260 cy/step @ ~1GHz idle clock). R4: MUFU.TANH replaces EX2+RCP chains
// (sigmoid via 0.5+0.5*tanh(x/2), with the 0.5 pre-scale folded into the
// weights), bias/x-term folded into accumulator init, fixed double buffers
// with explicit 2-step unroll.

#define T_MAX 8192
#define HID   40
#define NROW  160   // 4*HID

// d += a * b, packed 2xf32 (SASS FFMA2)
__device__ __forceinline__ void ffma2(uint64_t& d, uint64_t a, uint64_t b) {
    asm("fma.rn.f32x2 %0, %1, %2, %0;" : "+l"(d) : "l"(a), "l"(b));
}
__device__ __forceinline__ uint64_t fadd2(uint64_t a, uint64_t b) {
    uint64_t r;
    asm("add.rn.f32x2 %0, %1, %2;" : "=l"(r) : "l"(a), "l"(b));
    return r;
}
__device__ __forceinline__ void unpack2(float& lo, float& hi, uint64_t v) {
    asm("mov.b64 {%0, %1}, %2;" : "=f"(lo), "=f"(hi) : "l"(v));
}
__device__ __forceinline__ uint64_t pack2(float lo, float hi) {
    uint64_t r;
    asm("mov.b64 %0, {%1, %2};" : "=l"(r) : "f"(lo), "f"(hi));
    return r;
}
// Single-MUFU tanh (sm_75+): abs err ~2^-11, fine vs 1e-3 gate (monitored)
__device__ __forceinline__ float tanhapx(float x) {
    float r; asm("tanh.approx.f32 %0, %1;" : "=f"(r) : "f"(x)); return r;
}

__global__ __launch_bounds__(NROW, 1)
void lstm_seq_kernel(const float* __restrict__ x,
                     const float* __restrict__ W_ih,
                     const float* __restrict__ W_hh,
                     const float* __restrict__ b_ih,
                     const float* __restrict__ b_hh,
                     const float* __restrict__ W_lin,
                     const float* __restrict__ b_lin,
                     float* __restrict__ out,
                     int T)
{
    __shared__ float      xs[T_MAX];
    __shared__ ulonglong2 h0[HID / 4];   // fixed double buffers
    __shared__ ulonglong2 h1[HID / 4];

    const int tid  = threadIdx.x;
    const int w    = tid >> 5;
    const int lane = tid & 31;
    const int gate = lane >> 3;         // 0:i 1:f 2:g 3:o
    const int uu   = lane & 7;
    const int unit = w * 8 + uu;        // 0..39
    const int row  = gate * HID + unit; // 0..159

    // Stage the whole input sequence into shared once.
    for (int i = tid; i < T && i < T_MAX; i += NROW) xs[i] = x[i];

    // Activation plan: act = A * tanh(acc') + B, where acc' is the
    // pre-activation computed with PRE-SCALED weights:
    //   gates i,f,o: scale 0.5 -> act = 0.5*tanh(0.5*z)+0.5 = sigmoid(z)
    //   gate  g    : scale 1.0 -> act = tanh(z)
    const float scale = (gate == 2) ? 1.0f : 0.5f;
    const float A     = (gate == 2) ? 1.0f : 0.5f;
    const float B     = (gate == 2) ? 0.0f : 0.5f;

    // Per-thread recurrent weight row, pre-scaled, as 20 packed f32x2 pairs.
    uint64_t wp[HID / 2];
    {
        const float4* wrow = reinterpret_cast<const float4*>(W_hh + row * HID);
        #pragma unroll
        for (int k = 0; k < HID / 4; k++) {
            float4 v = wrow[k];
            wp[2 * k]     = pack2(v.x * scale, v.y * scale);
            wp[2 * k + 1] = pack2(v.z * scale, v.w * scale);
        }
    }
    const float wih  = W_ih[row] * scale;
    const float bias = (b_ih[row] + b_hh[row]) * scale;

    if (tid < HID / 4) h0[tid] = make_ulonglong2(0ull, 0ull);
    float c = 0.0f;   // cell state, owned by gate==0 lanes
    __syncthreads();

    const unsigned FULL = 0xffffffffu;

    auto step = [&](const ulonglong2* __restrict__ hin,
                    float* __restrict__ hout, int t) {
        // x/bias term folded into accumulator 0's init (off critical path:
        // independent of the h loads).
        uint64_t a0 = pack2(fmaf(xs[t], wih, bias), 0.0f);
        uint64_t a1 = 0ull, a2 = 0ull, a3 = 0ull;
        #pragma unroll
        for (int k = 0; k < HID / 4; k += 2) {
            ulonglong2 hv0 = hin[k];
            ulonglong2 hv1 = hin[k + 1];
            ffma2(a0, wp[2 * k],     hv0.x);
            ffma2(a1, wp[2 * k + 1], hv0.y);
            ffma2(a2, wp[2 * k + 2], hv1.x);
            ffma2(a3, wp[2 * k + 3], hv1.y);
        }
        uint64_t s = fadd2(fadd2(a0, a2), fadd2(a1, a3));
        float s0, s1;
        unpack2(s0, s1, s);
        float acc = s0 + s1;

        // One MUFU on the critical path for all four gates.
        float act = fmaf(A, tanhapx(acc), B);

        // Exchange ACTIVATED gate values within the warp.
        float f_ = __shfl_sync(FULL, act, uu + 8);
        float g_ = __shfl_sync(FULL, act, uu + 16);
        float o_ = __shfl_sync(FULL, act, uu + 24);

        if (gate == 0) {
            c = fmaf(f_, c, act * g_);      // act == i
            hout[unit] = o_ * tanhapx(c);
        }
        __syncthreads();
    };

    for (int t = 0; t + 1 < T; t += 2) {
        step(h0, reinterpret_cast<float*>(h1), t);
        step(h1, reinterpret_cast<float*>(h0), t + 1);
    }
    const float* hf = reinterpret_cast<const float*>(h0);
    if (T & 1) {
        step(h0, reinterpret_cast<float*>(h1), T - 1);
        hf = reinterpret_cast<const float*>(h1);
    }

    // Final linear: out = h_T . W_lin + b_lin (one-time cost).
    if (tid == 0) {
        float sum = b_lin[0];
        #pragma unroll
        for (int k = 0; k < HID; k++) sum = fmaf(hf[k], W_lin[k], sum);
        out[0] = sum;
    }
}

extern "C" void kernel_launch(void* const* d_in, const int* in_sizes, int n_in,
                              void* d_out, int out_size)
{
    const float* x     = (const float*)d_in[0]; // input_seq [T,1]
    const float* W_ih  = (const float*)d_in[1]; // [160,1]
    const float* W_hh  = (const float*)d_in[2]; // [160,40]
    const float* b_ih  = (const float*)d_in[3]; // [160]
    const float* b_hh  = (const float*)d_in[4]; // [160]
    const float* W_lin = (const float*)d_in[5]; // [1,40]
    const float* b_lin = (const float*)d_in[6]; // [1]
    float* out = (float*)d_out;

    int T = in_sizes[0];
    lstm_seq_kernel<<<1, NROW>>>(x, W_ih, W_hh, b_ih, b_hh, W_lin, b_lin, out, T);
}